// round 15
// baseline (speedup 1.0000x reference)
#include <cuda_runtime.h>
#include <cstdint>

// Problem constants
#define BB   16
#define CC   256
#define HH   64
#define WW   64
#define HWSZ 4096     // H*W
#define DQ   32       // C/8
#define DV   128      // C/2
#define OC   192      // 2*DQ + DV
#define MM   1024     // pooled spatial (32*32)

// Scratch (device globals)
// g_q  : q channels fp32 [b][d][hw]
// g_k  : pooled K fp32 [b][m][pd]      (pd = pair-permuted d within 8-groups)
// g_v2 : pooled V fp16x2 [b][d][u]     (u = half2 unit = m/2, slot-permuted within 8-unit groups)
// g_wo2: w_out fp16x2 [c][du]          (du = half2 unit = d/2, slot-permuted within 8-unit groups)
// slot-perm within 8: slot s holds unit {0,4,1,5,2,6,3,7}[s]
__device__ float    g_q  [BB * DQ * HWSZ];
__device__ float    g_k  [BB * MM * DQ];
__device__ uint32_t g_v2 [BB * DV * (MM / 2)];
__device__ uint32_t g_wo2[CC * (DV / 2)];

// ---- mma helpers (baseline ISA) ----
// tf32, raw fp32 bits in operands (HMMA reads tf32 subset)
__device__ __forceinline__ void mma_tf32(float* c, const uint32_t* a, const uint32_t* b) {
    asm volatile("mma.sync.aligned.m16n8k8.row.col.f32.tf32.tf32.f32 "
        "{%0,%1,%2,%3}, {%4,%5,%6,%7}, {%8,%9}, {%0,%1,%2,%3};"
        : "+f"(c[0]), "+f"(c[1]), "+f"(c[2]), "+f"(c[3])
        : "r"(a[0]), "r"(a[1]), "r"(a[2]), "r"(a[3]), "r"(b[0]), "r"(b[1]));
}
// fp16 in, fp32 accum
__device__ __forceinline__ void mma_f16(float* c, uint32_t a0, uint32_t a1, uint32_t a2,
                                        uint32_t a3, uint32_t b0, uint32_t b1) {
    asm volatile("mma.sync.aligned.m16n8k16.row.col.f32.f16.f16.f32 "
        "{%0,%1,%2,%3}, {%4,%5,%6,%7}, {%8,%9}, {%0,%1,%2,%3};"
        : "+f"(c[0]), "+f"(c[1]), "+f"(c[2]), "+f"(c[3])
        : "r"(a0), "r"(a1), "r"(a2), "r"(a3), "r"(b0), "r"(b1));
}
// pack half2: lo = first arg
__device__ __forceinline__ uint32_t pack_h2(float lo, float hi) {
    uint32_t r;
    asm("cvt.rn.f16x2.f32 %0, %1, %2;" : "=r"(r) : "f"(hi), "f"(lo));
    return r;
}

// ---- cp.async helpers ----
__device__ __forceinline__ void cp16(void* dst, const void* src) {
    uint32_t d = (uint32_t)__cvta_generic_to_shared(dst);
    asm volatile("cp.async.cg.shared.global [%0], [%1], 16;" :: "r"(d), "l"(src) : "memory");
}
#define CP_COMMIT() asm volatile("cp.async.commit_group;" ::: "memory")
#define CP_WAIT0()  asm volatile("cp.async.wait_group 0;" ::: "memory")
#define CP_WAIT1()  asm volatile("cp.async.wait_group 1;" ::: "memory")

extern __shared__ uint32_t dynsm[];

// ============================================================
// K1: qkv GEMM (tf32) + fused 2x2 maxpool epilogue.
// by=0: rows 0-31 q -> g_q; rows 32-63 k -> pool -> g_k (fp32, pd-perm)
// by=1/2: v chans -> pool -> g_v2 (fp16x2, unit-perm)
// ALSO: 16 CTAs (by=0, bx=0) pack w_out fp32 -> g_wo2 fp16 for the fused proj.
// ============================================================
#define G_SA(i) ((i) * 2304)              // 64*36
#define G_SB(i) (4608 + (i) * 8448)       // 32*264
#define GEMM_SMEM_BYTES ((4608 + 2 * 8448) * 4)   // 86016

__global__ void __launch_bounds__(256) k_qkv_mma(const float* __restrict__ imgs,
                                                 const float* __restrict__ wq,
                                                 const float* __restrict__ wout) {
    const int b  = blockIdx.z;
    const int o0 = blockIdx.y * 64;
    const int n0 = blockIdx.x * 256;
    const int tid = threadIdx.x, lane = tid & 31, wid = tid >> 5;
    const int lr = lane >> 2, lc = lane & 3;
    const int wm = (wid >> 2) * 32;
    const int wn = (wid & 3) * 64;
    const float* X = imgs + (size_t)b * CC * HWSZ;

    auto prefetch = [&](int ibuf, int kc) {
        uint32_t* sA = dynsm + G_SA(ibuf);
        uint32_t* sB = dynsm + G_SB(ibuf);
#pragma unroll
        for (int it = 0; it < 2; it++) {
            int u = tid + it * 256;
            int o = u >> 3, cv = u & 7;
            cp16(&sA[o * 36 + cv * 4], wq + (size_t)(o0 + o) * CC + kc + cv * 4);
        }
#pragma unroll
        for (int it = 0; it < 8; it++) {
            int u = tid + it * 256;
            int c = u >> 6, nv = u & 63;
            cp16(&sB[c * 264 + nv * 4], X + (size_t)(kc + c) * HWSZ + n0 + nv * 4);
        }
        CP_COMMIT();
    };

    float acc[2][8][4];
#pragma unroll
    for (int mf = 0; mf < 2; mf++)
#pragma unroll
        for (int nf = 0; nf < 8; nf++)
#pragma unroll
            for (int j = 0; j < 4; j++) acc[mf][nf][j] = 0.0f;

    prefetch(0, 0);

    // w_out fp16 packing: 16 CTAs (one per b), rows [b*16, b*16+16)
    if (o0 == 0 && blockIdx.x == 0) {
#pragma unroll
        for (int i = 0; i < 4; i++) {
            int idx = tid + i * 256;                 // 1024 words
            int c  = b * 16 + (idx >> 6);
            int gu = idx & 63;
            int g = gu >> 3, sl = gu & 7;
            int pu = (sl & 1) ? (sl >> 1) + 4 : (sl >> 1);
            int cu = g * 8 + pu;
            float2 w2 = *(const float2*)&wout[(size_t)c * DV + 2 * cu];
            g_wo2[c * 64 + gu] = pack_h2(w2.x, w2.y);
        }
    }

    for (int ic = 0; ic < 8; ic++) {
        if (ic + 1 < 8) { prefetch((ic + 1) & 1, (ic + 1) * 32); CP_WAIT1(); }
        else            { CP_WAIT0(); }
        __syncthreads();
        const uint32_t* sA = dynsm + G_SA(ic & 1);
        const uint32_t* sB = dynsm + G_SB(ic & 1);
#pragma unroll
        for (int k8 = 0; k8 < 32; k8 += 8) {
            uint32_t a[2][4];
            const int ar = wm + lr;
            const int ac = k8 + lc;
#pragma unroll
            for (int mf = 0; mf < 2; mf++) {
                int r = ar + mf * 16;
                a[mf][0] = sA[r * 36 + ac];
                a[mf][1] = sA[(r + 8) * 36 + ac];
                a[mf][2] = sA[r * 36 + ac + 4];
                a[mf][3] = sA[(r + 8) * 36 + ac + 4];
            }
#pragma unroll
            for (int nf = 0; nf < 8; nf++) {
                int bn = wn + nf * 8 + lr;
                uint32_t bf[2];
                bf[0] = sB[(k8 + lc) * 264 + bn];
                bf[1] = sB[(k8 + 4 + lc) * 264 + bn];
                mma_tf32(acc[0][nf], a[0], bf);
                mma_tf32(acc[1][nf], a[1], bf);
            }
        }
        __syncthreads();
    }

    // -------- fused epilogue --------
    float* stg = (float*)dynsm;                 // [rows][260]
    const int bxm = blockIdx.x * 64;            // pooled-m base of this CTA

    if (o0 == 0) {
        if (wm == 0) {
            // warps 0-3: q rows 0..31 -> g_q
#pragma unroll
            for (int mf = 0; mf < 2; mf++)
#pragma unroll
                for (int nf = 0; nf < 8; nf++) {
                    int row = mf * 16 + lr;
                    int col = wn + nf * 8 + 2 * lc;
                    *(float2*)(g_q + ((size_t)b * DQ + row) * HWSZ + n0 + col) =
                        make_float2(acc[mf][nf][0], acc[mf][nf][1]);
                    *(float2*)(g_q + ((size_t)b * DQ + row + 8) * HWSZ + n0 + col) =
                        make_float2(acc[mf][nf][2], acc[mf][nf][3]);
                }
        } else {
            // warps 4-7: stage k rows (qkv rows 32..63 -> staged 0..31)
#pragma unroll
            for (int mf = 0; mf < 2; mf++)
#pragma unroll
                for (int nf = 0; nf < 8; nf++) {
                    int r   = mf * 16 + lr;
                    int col = wn + nf * 8 + 2 * lc;
                    *(float2*)&stg[r * 260 + col] =
                        make_float2(acc[mf][nf][0], acc[mf][nf][1]);
                    *(float2*)&stg[(r + 8) * 260 + col] =
                        make_float2(acc[mf][nf][2], acc[mf][nf][3]);
                }
        }
        __syncthreads();
        // pool K -> g_k[b][m][pd] fp32
        for (int e = tid; e < 32 * 64; e += 256) {
            int pd = e & 31, mloc = e >> 5;
            int p8 = pd & 7;
            int ch = (pd & ~7) + ((p8 & 1) ? (p8 >> 1) + 4 : (p8 >> 1));
            int myl = mloc >> 5, mx = mloc & 31;
            const float* s0 = stg + ch * 260 + myl * 128 + 2 * mx;
            float v = fmaxf(fmaxf(s0[0], s0[1]), fmaxf(s0[64], s0[65]));
            g_k[((size_t)b * MM + bxm + mloc) * DQ + pd] = v;
        }
    } else {
        const int chb = o0 - 64;     // v channel base (0 or 64)
#pragma unroll
        for (int mf = 0; mf < 2; mf++)
#pragma unroll
            for (int nf = 0; nf < 8; nf++) {
                int r   = wm + mf * 16 + lr;
                int col = wn + nf * 8 + 2 * lc;
                *(float2*)&stg[r * 260 + col] =
                    make_float2(acc[mf][nf][0], acc[mf][nf][1]);
                *(float2*)&stg[(r + 8) * 260 + col] =
                    make_float2(acc[mf][nf][2], acc[mf][nf][3]);
            }
        __syncthreads();
        // pool V -> g_v2[b][d][unit-slot] fp16x2, slot-permuted
        for (int e = tid; e < 64 * 32; e += 256) {
            int sl = e & 31, ch = e >> 5;
            int g = sl >> 3, p = sl & 7;
            int unit = g * 8 + ((p & 1) ? (p >> 1) + 4 : (p >> 1));
            float vv[2];
#pragma unroll
            for (int h = 0; h < 2; h++) {
                int mloc = 2 * unit + h;
                int myl = mloc >> 5, mx = mloc & 31;
                const float* s0 = stg + ch * 260 + myl * 128 + 2 * mx;
                vv[h] = fmaxf(fmaxf(s0[0], s0[1]), fmaxf(s0[64], s0[65]));
            }
            g_v2[((size_t)b * DV + chb + ch) * (MM / 2) + blockIdx.x * 32 + sl] =
                pack_h2(vv[0], vv[1]);
        }
    }
}

// ============================================================
// K3: flash attention + FUSED output projection + residual.
// S in tf32, PV in fp16, proj in fp16. CTA 256 thr = 8 warps x 16q,
// 128-query tile, grid (32,16), 2 CTA/SM.
// Main loop SMEM (words): sQ[32][132] | sK 2x[64][40] | sV 2x[128][40] | sE[128][40]
// Epilogue SMEM: Os[128 q][72] (words 0..9216) | sW[256 c][72] (9216..27648)
// ============================================================
#define AQ 0
#define AK 4224
#define AV 9344
#define AE 19584
#define SW_OFF 9216
#define SATT_SMEM_BYTES ((SW_OFF + 256 * 72) * 4)    // 110592

__global__ void __launch_bounds__(256, 2) k_attn_mma(const float* __restrict__ imgs,
                                                     const float* __restrict__ scale_p,
                                                     float* __restrict__ out) {
    uint32_t* sQ = dynsm + AQ;
    uint32_t* sE = dynsm + AE;

    const int b   = blockIdx.y;
    const int n0  = blockIdx.x * 128;
    const int tid = threadIdx.x, lane = tid & 31, wid = tid >> 5;
    const int qb  = wid * 16;
    const int lr  = lane >> 2;
    const int lc  = lane & 3;

    // tile loaders
    auto load_k = [&](int mt) {
        uint32_t* dst = dynsm + AK + (mt & 1) * 2560;
#pragma unroll
        for (int it = 0; it < 2; it++) {
            int u = tid + it * 256;
            int ml = u >> 3, c = u & 7;
            cp16(&dst[ml * 40 + c * 4], g_k + ((size_t)b * MM + mt * 64 + ml) * DQ + c * 4);
        }
    };
    auto load_v = [&](int mt) {
        uint32_t* dst = dynsm + AV + (mt & 1) * 5120;
#pragma unroll
        for (int it = 0; it < 4; it++) {
            int u = tid + it * 256;
            int d = u >> 3, c = u & 7;
            cp16(&dst[d * 40 + c * 4],
                 g_v2 + ((size_t)b * DV + d) * (MM / 2) + mt * 32 + c * 4);
        }
    };

    // prologue: Q + K0 + V0
#pragma unroll
    for (int it = 0; it < 4; it++) {
        int u = tid + it * 256;
        int d = u >> 5, nv = u & 31;
        cp16(&sQ[d * 132 + nv * 4], g_q + ((size_t)b * DQ + d) * HWSZ + n0 + nv * 4);
    }
    load_k(0);
    load_v(0);
    CP_COMMIT();
    CP_WAIT0();
    __syncthreads();

    // preload Q A-fragments (tf32)
    uint32_t qa[4][4];
#pragma unroll
    for (int ks = 0; ks < 4; ks++) {
        int d = ks * 8 + lc;
        qa[ks][0] = sQ[d * 132 + qb + lr];
        qa[ks][1] = sQ[d * 132 + qb + lr + 8];
        qa[ks][2] = sQ[(d + 4) * 132 + qb + lr];
        qa[ks][3] = sQ[(d + 4) * 132 + qb + lr + 8];
    }

    float oacc[16][4];
#pragma unroll
    for (int nf = 0; nf < 16; nf++)
#pragma unroll
        for (int j = 0; j < 4; j++) oacc[nf][j] = 0.0f;
    float rs0 = 0.0f, rs1 = 0.0f;

    for (int mt = 0; mt < 16; mt++) {
        if (mt > 0) CP_WAIT0();   // drain K(mt),V(mt) prefetch
        __syncthreads();          // tiles visible; prev PV done (sE safe)

        // S = Q @ K_tile^T (tf32)
        const uint32_t* sK2 = dynsm + AK + (mt & 1) * 2560;
        float sf[8][4];
#pragma unroll
        for (int nf = 0; nf < 8; nf++)
#pragma unroll
            for (int j = 0; j < 4; j++) sf[nf][j] = 0.0f;
#pragma unroll
        for (int ks = 0; ks < 4; ks++) {
#pragma unroll
            for (int nf = 0; nf < 8; nf++) {
                const uint32_t* bp = &sK2[(nf * 8 + lr) * 40 + ks * 8 + 2 * lc];
                mma_tf32(sf[nf], qa[ks], bp);
            }
        }
        // exp + rowsum; store E as permuted half2
#pragma unroll
        for (int nf = 0; nf < 8; nf++) {
            float e0 = __expf(sf[nf][0]);
            float e1 = __expf(sf[nf][1]);
            float e2 = __expf(sf[nf][2]);
            float e3 = __expf(sf[nf][3]);
            rs0 += e0 + e1;
            rs1 += e2 + e3;
            int w = (nf >> 1) * 8 + 2 * lc + (nf & 1);   // slot of unit 4nf+lc
            sE[(qb + lr) * 40 + w]     = pack_h2(e0, e1);
            sE[(qb + lr + 8) * 40 + w] = pack_h2(e2, e3);
        }
        __syncthreads();          // sE complete

        // prefetch next tiles (overlaps PV)
        if (mt + 1 < 16) {
            load_k(mt + 1);
            load_v(mt + 1);
            CP_COMMIT();
        }

        // O += E @ V (fp16, 4 k16-steps x 16 d-frags)
        const uint32_t* sVb = dynsm + AV + (mt & 1) * 5120;
#pragma unroll
        for (int ks = 0; ks < 4; ks++) {
            uint2 eL = *(const uint2*)&sE[(qb + lr) * 40 + ks * 8 + 2 * lc];
            uint2 eH = *(const uint2*)&sE[(qb + lr + 8) * 40 + ks * 8 + 2 * lc];
#pragma unroll
            for (int nf = 0; nf < 16; nf++) {
                uint2 bb = *(const uint2*)&sVb[(nf * 8 + lr) * 40 + ks * 8 + 2 * lc];
                mma_f16(oacc[nf], eL.x, eH.x, eL.y, eH.y, bb.x, bb.y);
            }
        }
    }
    __syncthreads();   // all PV done -> sK/sV/sE regions dead, safe for sW

    // issue w_out fp16 tile load into sW (overlaps normalize below)
    uint32_t* sW = dynsm + SW_OFF;    // [256 c][72]
#pragma unroll
    for (int it = 0; it < 16; it++) {
        int u = tid + it * 256;
        int c = u >> 4, seg = u & 15;
        cp16(&sW[c * 72 + seg * 4], g_wo2 + c * 64 + seg * 4);
    }
    CP_COMMIT();

    // rowsum reduce across quad lanes
    rs0 += __shfl_xor_sync(0xffffffffu, rs0, 1);
    rs0 += __shfl_xor_sync(0xffffffffu, rs0, 2);
    rs1 += __shfl_xor_sync(0xffffffffu, rs1, 1);
    rs1 += __shfl_xor_sync(0xffffffffu, rs1, 2);
    const float inv0 = 1.0f / rs0, inv1 = 1.0f / rs1;

    // Normalize, pack half2 (d-pairs native in C-frag), stage permuted [q][72]
    uint32_t* Os = dynsm;   // 128*72 = 9216 words, overlays sQ/sK (dead)
#pragma unroll
    for (int nf = 0; nf < 16; nf++) {
        int w = (nf >> 1) * 8 + 2 * lc + (nf & 1);   // slot of unit 4nf+lc (of 64)
        Os[(qb + lr) * 72 + w]     = pack_h2(oacc[nf][0] * inv0, oacc[nf][1] * inv0);
        Os[(qb + lr + 8) * 72 + w] = pack_h2(oacc[nf][2] * inv1, oacc[nf][3] * inv1);
    }
    CP_WAIT0();
    __syncthreads();        // Os + sW visible to all warps

    // -------- fused projection + residual --------
    // out[c][q] = imgs[c][q] + s * sum_d wout[c][d] * O[d][q]
    // two passes of 128 channels; warp w owns c rows [p*128 + w*16, +16)
    const float s = *scale_p;
#pragma unroll
    for (int p = 0; p < 2; p++) {
        const int cb = p * 128 + wid * 16;
        float pacc[16][4];
#pragma unroll
        for (int nf = 0; nf < 16; nf++)
#pragma unroll
            for (int j = 0; j < 4; j++) pacc[nf][j] = 0.0f;
#pragma unroll
        for (int ks = 0; ks < 8; ks++) {
            uint2 aL = *(const uint2*)&sW[(cb + lr) * 72 + ks * 8 + 2 * lc];
            uint2 aH = *(const uint2*)&sW[(cb + lr + 8) * 72 + ks * 8 + 2 * lc];
#pragma unroll
            for (int nf = 0; nf < 16; nf++) {
                uint2 bb = *(const uint2*)&Os[(nf * 8 + lr) * 72 + ks * 8 + 2 * lc];
                mma_f16(pacc[nf], aL.x, aH.x, aL.y, aH.y, bb.x, bb.y);
            }
        }
#pragma unroll
        for (int nf = 0; nf < 16; nf++) {
            int col = nf * 8 + 2 * lc;
            size_t i0 = ((size_t)b * CC + cb + lr) * HWSZ + n0 + col;
            size_t i1 = ((size_t)b * CC + cb + lr + 8) * HWSZ + n0 + col;
            float2 m0 = *(const float2*)&imgs[i0];
            float2 m1 = *(const float2*)&imgs[i1];
            *(float2*)&out[i0] = make_float2(m0.x + s * pacc[nf][0],
                                             m0.y + s * pacc[nf][1]);
            *(float2*)&out[i1] = make_float2(m1.x + s * pacc[nf][2],
                                             m1.y + s * pacc[nf][3]);
        }
    }
}

// ============================================================
extern "C" void kernel_launch(void* const* d_in, const int* in_sizes, int n_in,
                              void* d_out, int out_size) {
    const float* imgs  = (const float*)d_in[0];
    const float* wqkv  = (const float*)d_in[1];
    const float* wout  = (const float*)d_in[2];
    const float* scale = (const float*)d_in[3];
    float* out = (float*)d_out;

    cudaFuncSetAttribute(k_qkv_mma,  cudaFuncAttributeMaxDynamicSharedMemorySize, GEMM_SMEM_BYTES);
    cudaFuncSetAttribute(k_attn_mma, cudaFuncAttributeMaxDynamicSharedMemorySize, SATT_SMEM_BYTES);

    k_qkv_mma<<<dim3(16, 3, 16), 256, GEMM_SMEM_BYTES>>>(imgs, wqkv, wout);

    k_attn_mma<<<dim3(32, 16), 256, SATT_SMEM_BYTES>>>(imgs, scale, out);
}

// round 16
// speedup vs baseline: 1.0213x; 1.0213x over previous
#include <cuda_runtime.h>
#include <cstdint>

// Problem constants
#define BB   16
#define CC   256
#define HH   64
#define WW   64
#define HWSZ 4096     // H*W
#define DQ   32       // C/8
#define DV   128      // C/2
#define OC   192      // 2*DQ + DV
#define MM   1024     // pooled spatial (32*32)

// Scratch (device globals)
// g_q  : q channels fp32 [b][d][hw]
// g_k  : pooled K fp32 [b][m][pd]      (pd = pair-permuted d within 8-groups)
// g_v2 : pooled V fp16x2 [b][d][u]     (u = half2 unit = m/2, slot-permuted within 8-unit groups)
// g_wo2: w_out fp16x2 [c][du]          (du = half2 unit = d/2, slot-permuted within 8-unit groups)
// slot-perm within 8: slot s holds unit {0,4,1,5,2,6,3,7}[s]
__device__ float    g_q  [BB * DQ * HWSZ];
__device__ float    g_k  [BB * MM * DQ];
__device__ uint32_t g_v2 [BB * DV * (MM / 2)];
__device__ uint32_t g_wo2[CC * (DV / 2)];

// ---- mma helpers (baseline ISA) ----
// tf32, raw fp32 bits in operands (HMMA reads tf32 subset)
__device__ __forceinline__ void mma_tf32(float* c, const uint32_t* a, const uint32_t* b) {
    asm volatile("mma.sync.aligned.m16n8k8.row.col.f32.tf32.tf32.f32 "
        "{%0,%1,%2,%3}, {%4,%5,%6,%7}, {%8,%9}, {%0,%1,%2,%3};"
        : "+f"(c[0]), "+f"(c[1]), "+f"(c[2]), "+f"(c[3])
        : "r"(a[0]), "r"(a[1]), "r"(a[2]), "r"(a[3]), "r"(b[0]), "r"(b[1]));
}
// fp16 in, fp32 accum
__device__ __forceinline__ void mma_f16(float* c, uint32_t a0, uint32_t a1, uint32_t a2,
                                        uint32_t a3, uint32_t b0, uint32_t b1) {
    asm volatile("mma.sync.aligned.m16n8k16.row.col.f32.f16.f16.f32 "
        "{%0,%1,%2,%3}, {%4,%5,%6,%7}, {%8,%9}, {%0,%1,%2,%3};"
        : "+f"(c[0]), "+f"(c[1]), "+f"(c[2]), "+f"(c[3])
        : "r"(a0), "r"(a1), "r"(a2), "r"(a3), "r"(b0), "r"(b1));
}
// pack half2: lo = first arg
__device__ __forceinline__ uint32_t pack_h2(float lo, float hi) {
    uint32_t r;
    asm("cvt.rn.f16x2.f32 %0, %1, %2;" : "=r"(r) : "f"(hi), "f"(lo));
    return r;
}

// ---- cp.async helpers ----
__device__ __forceinline__ void cp16(void* dst, const void* src) {
    uint32_t d = (uint32_t)__cvta_generic_to_shared(dst);
    asm volatile("cp.async.cg.shared.global [%0], [%1], 16;" :: "r"(d), "l"(src) : "memory");
}
#define CP_COMMIT() asm volatile("cp.async.commit_group;" ::: "memory")
#define CP_WAIT0()  asm volatile("cp.async.wait_group 0;" ::: "memory")
#define CP_WAIT1()  asm volatile("cp.async.wait_group 1;" ::: "memory")

extern __shared__ uint32_t dynsm[];

// ============================================================
// K1: qkv GEMM (tf32) + fused 2x2 maxpool epilogue. (unchanged from R15)
// ============================================================
#define G_SA(i) ((i) * 2304)              // 64*36
#define G_SB(i) (4608 + (i) * 8448)       // 32*264
#define GEMM_SMEM_BYTES ((4608 + 2 * 8448) * 4)   // 86016

__global__ void __launch_bounds__(256) k_qkv_mma(const float* __restrict__ imgs,
                                                 const float* __restrict__ wq,
                                                 const float* __restrict__ wout) {
    const int b  = blockIdx.z;
    const int o0 = blockIdx.y * 64;
    const int n0 = blockIdx.x * 256;
    const int tid = threadIdx.x, lane = tid & 31, wid = tid >> 5;
    const int lr = lane >> 2, lc = lane & 3;
    const int wm = (wid >> 2) * 32;
    const int wn = (wid & 3) * 64;
    const float* X = imgs + (size_t)b * CC * HWSZ;

    auto prefetch = [&](int ibuf, int kc) {
        uint32_t* sA = dynsm + G_SA(ibuf);
        uint32_t* sB = dynsm + G_SB(ibuf);
#pragma unroll
        for (int it = 0; it < 2; it++) {
            int u = tid + it * 256;
            int o = u >> 3, cv = u & 7;
            cp16(&sA[o * 36 + cv * 4], wq + (size_t)(o0 + o) * CC + kc + cv * 4);
        }
#pragma unroll
        for (int it = 0; it < 8; it++) {
            int u = tid + it * 256;
            int c = u >> 6, nv = u & 63;
            cp16(&sB[c * 264 + nv * 4], X + (size_t)(kc + c) * HWSZ + n0 + nv * 4);
        }
        CP_COMMIT();
    };

    float acc[2][8][4];
#pragma unroll
    for (int mf = 0; mf < 2; mf++)
#pragma unroll
        for (int nf = 0; nf < 8; nf++)
#pragma unroll
            for (int j = 0; j < 4; j++) acc[mf][nf][j] = 0.0f;

    prefetch(0, 0);

    // w_out fp16 packing: 16 CTAs (one per b), rows [b*16, b*16+16)
    if (o0 == 0 && blockIdx.x == 0) {
#pragma unroll
        for (int i = 0; i < 4; i++) {
            int idx = tid + i * 256;                 // 1024 words
            int c  = b * 16 + (idx >> 6);
            int gu = idx & 63;
            int g = gu >> 3, sl = gu & 7;
            int pu = (sl & 1) ? (sl >> 1) + 4 : (sl >> 1);
            int cu = g * 8 + pu;
            float2 w2 = *(const float2*)&wout[(size_t)c * DV + 2 * cu];
            g_wo2[c * 64 + gu] = pack_h2(w2.x, w2.y);
        }
    }

    for (int ic = 0; ic < 8; ic++) {
        if (ic + 1 < 8) { prefetch((ic + 1) & 1, (ic + 1) * 32); CP_WAIT1(); }
        else            { CP_WAIT0(); }
        __syncthreads();
        const uint32_t* sA = dynsm + G_SA(ic & 1);
        const uint32_t* sB = dynsm + G_SB(ic & 1);
#pragma unroll
        for (int k8 = 0; k8 < 32; k8 += 8) {
            uint32_t a[2][4];
            const int ar = wm + lr;
            const int ac = k8 + lc;
#pragma unroll
            for (int mf = 0; mf < 2; mf++) {
                int r = ar + mf * 16;
                a[mf][0] = sA[r * 36 + ac];
                a[mf][1] = sA[(r + 8) * 36 + ac];
                a[mf][2] = sA[r * 36 + ac + 4];
                a[mf][3] = sA[(r + 8) * 36 + ac + 4];
            }
#pragma unroll
            for (int nf = 0; nf < 8; nf++) {
                int bn = wn + nf * 8 + lr;
                uint32_t bf[2];
                bf[0] = sB[(k8 + lc) * 264 + bn];
                bf[1] = sB[(k8 + 4 + lc) * 264 + bn];
                mma_tf32(acc[0][nf], a[0], bf);
                mma_tf32(acc[1][nf], a[1], bf);
            }
        }
        __syncthreads();
    }

    // -------- fused epilogue --------
    float* stg = (float*)dynsm;                 // [rows][260]
    const int bxm = blockIdx.x * 64;            // pooled-m base of this CTA

    if (o0 == 0) {
        if (wm == 0) {
            // warps 0-3: q rows 0..31 -> g_q
#pragma unroll
            for (int mf = 0; mf < 2; mf++)
#pragma unroll
                for (int nf = 0; nf < 8; nf++) {
                    int row = mf * 16 + lr;
                    int col = wn + nf * 8 + 2 * lc;
                    *(float2*)(g_q + ((size_t)b * DQ + row) * HWSZ + n0 + col) =
                        make_float2(acc[mf][nf][0], acc[mf][nf][1]);
                    *(float2*)(g_q + ((size_t)b * DQ + row + 8) * HWSZ + n0 + col) =
                        make_float2(acc[mf][nf][2], acc[mf][nf][3]);
                }
        } else {
            // warps 4-7: stage k rows (qkv rows 32..63 -> staged 0..31)
#pragma unroll
            for (int mf = 0; mf < 2; mf++)
#pragma unroll
                for (int nf = 0; nf < 8; nf++) {
                    int r   = mf * 16 + lr;
                    int col = wn + nf * 8 + 2 * lc;
                    *(float2*)&stg[r * 260 + col] =
                        make_float2(acc[mf][nf][0], acc[mf][nf][1]);
                    *(float2*)&stg[(r + 8) * 260 + col] =
                        make_float2(acc[mf][nf][2], acc[mf][nf][3]);
                }
        }
        __syncthreads();
        // pool K -> g_k[b][m][pd] fp32
        for (int e = tid; e < 32 * 64; e += 256) {
            int pd = e & 31, mloc = e >> 5;
            int p8 = pd & 7;
            int ch = (pd & ~7) + ((p8 & 1) ? (p8 >> 1) + 4 : (p8 >> 1));
            int myl = mloc >> 5, mx = mloc & 31;
            const float* s0 = stg + ch * 260 + myl * 128 + 2 * mx;
            float v = fmaxf(fmaxf(s0[0], s0[1]), fmaxf(s0[64], s0[65]));
            g_k[((size_t)b * MM + bxm + mloc) * DQ + pd] = v;
        }
    } else {
        const int chb = o0 - 64;     // v channel base (0 or 64)
#pragma unroll
        for (int mf = 0; mf < 2; mf++)
#pragma unroll
            for (int nf = 0; nf < 8; nf++) {
                int r   = wm + mf * 16 + lr;
                int col = wn + nf * 8 + 2 * lc;
                *(float2*)&stg[r * 260 + col] =
                    make_float2(acc[mf][nf][0], acc[mf][nf][1]);
                *(float2*)&stg[(r + 8) * 260 + col] =
                    make_float2(acc[mf][nf][2], acc[mf][nf][3]);
            }
        __syncthreads();
        // pool V -> g_v2[b][d][unit-slot] fp16x2, slot-permuted
        for (int e = tid; e < 64 * 32; e += 256) {
            int sl = e & 31, ch = e >> 5;
            int g = sl >> 3, p = sl & 7;
            int unit = g * 8 + ((p & 1) ? (p >> 1) + 4 : (p >> 1));
            float vv[2];
#pragma unroll
            for (int h = 0; h < 2; h++) {
                int mloc = 2 * unit + h;
                int myl = mloc >> 5, mx = mloc & 31;
                const float* s0 = stg + ch * 260 + myl * 128 + 2 * mx;
                vv[h] = fmaxf(fmaxf(s0[0], s0[1]), fmaxf(s0[64], s0[65]));
            }
            g_v2[((size_t)b * DV + chb + ch) * (MM / 2) + blockIdx.x * 32 + sl] =
                pack_h2(vv[0], vv[1]);
        }
    }
}

// ============================================================
// K3: flash attention + fused projection + residual.
// E NEVER TOUCHES SMEM: the S C-frag -> PV A-frag mapping is thread-local
// (slot perm verified: store slot (nf>>1)*8+2lc+(nf&1) == load slot
// ks*8+2lc/+1 for nf=2ks/2ks+1, same (lr,lc) thread), so exp results are
// packed to half2 registers and fed straight into mma. One barrier/iter.
// Main loop SMEM (words): sQ[32][132] | sK 2x[64][40] | sV 2x[128][40]
// Epilogue SMEM: Os[128 q][72] (0..9216) | sW[256 c][72] (9216..27648)
// ============================================================
#define AQ 0
#define AK 4224
#define AV 9344
#define SW_OFF 9216
#define SATT_SMEM_BYTES ((SW_OFF + 256 * 72) * 4)    // 110592

__global__ void __launch_bounds__(256, 2) k_attn_mma(const float* __restrict__ imgs,
                                                     const float* __restrict__ scale_p,
                                                     float* __restrict__ out) {
    uint32_t* sQ = dynsm + AQ;

    const int b   = blockIdx.y;
    const int n0  = blockIdx.x * 128;
    const int tid = threadIdx.x, lane = tid & 31, wid = tid >> 5;
    const int qb  = wid * 16;
    const int lr  = lane >> 2;
    const int lc  = lane & 3;

    // tile loaders
    auto load_k = [&](int mt) {
        uint32_t* dst = dynsm + AK + (mt & 1) * 2560;
#pragma unroll
        for (int it = 0; it < 2; it++) {
            int u = tid + it * 256;
            int ml = u >> 3, c = u & 7;
            cp16(&dst[ml * 40 + c * 4], g_k + ((size_t)b * MM + mt * 64 + ml) * DQ + c * 4);
        }
    };
    auto load_v = [&](int mt) {
        uint32_t* dst = dynsm + AV + (mt & 1) * 5120;
#pragma unroll
        for (int it = 0; it < 4; it++) {
            int u = tid + it * 256;
            int d = u >> 3, c = u & 7;
            cp16(&dst[d * 40 + c * 4],
                 g_v2 + ((size_t)b * DV + d) * (MM / 2) + mt * 32 + c * 4);
        }
    };

    // prologue: Q + K0 + V0
#pragma unroll
    for (int it = 0; it < 4; it++) {
        int u = tid + it * 256;
        int d = u >> 5, nv = u & 31;
        cp16(&sQ[d * 132 + nv * 4], g_q + ((size_t)b * DQ + d) * HWSZ + n0 + nv * 4);
    }
    load_k(0);
    load_v(0);
    CP_COMMIT();
    CP_WAIT0();
    __syncthreads();

    // preload Q A-fragments (tf32)
    uint32_t qa[4][4];
#pragma unroll
    for (int ks = 0; ks < 4; ks++) {
        int d = ks * 8 + lc;
        qa[ks][0] = sQ[d * 132 + qb + lr];
        qa[ks][1] = sQ[d * 132 + qb + lr + 8];
        qa[ks][2] = sQ[(d + 4) * 132 + qb + lr];
        qa[ks][3] = sQ[(d + 4) * 132 + qb + lr + 8];
    }

    float oacc[16][4];
#pragma unroll
    for (int nf = 0; nf < 16; nf++)
#pragma unroll
        for (int j = 0; j < 4; j++) oacc[nf][j] = 0.0f;
    float rs0 = 0.0f, rs1 = 0.0f;

    for (int mt = 0; mt < 16; mt++) {
        if (mt > 0) CP_WAIT0();   // drain K(mt),V(mt) prefetch
        __syncthreads();          // tiles visible; all warps done with other bufs

        // prefetch next tiles (buffer (mt+1)&1, last read in iter mt-1)
        if (mt + 1 < 16) {
            load_k(mt + 1);
            load_v(mt + 1);
            CP_COMMIT();
        }

        // S = Q @ K_tile^T (tf32)
        const uint32_t* sK2 = dynsm + AK + (mt & 1) * 2560;
        float sf[8][4];
#pragma unroll
        for (int nf = 0; nf < 8; nf++)
#pragma unroll
            for (int j = 0; j < 4; j++) sf[nf][j] = 0.0f;
#pragma unroll
        for (int ks = 0; ks < 4; ks++) {
#pragma unroll
            for (int nf = 0; nf < 8; nf++) {
                uint2 kb = *(const uint2*)&sK2[(nf * 8 + lr) * 40 + ks * 8 + 2 * lc];
                uint32_t bf[2] = { kb.x, kb.y };
                mma_tf32(sf[nf], qa[ks], bf);
            }
        }
        // exp + rowsum -> half2 REGISTERS (thread-local PV a-frags)
        uint32_t ehL[8], ehH[8];
#pragma unroll
        for (int nf = 0; nf < 8; nf++) {
            float e0 = __expf(sf[nf][0]);
            float e1 = __expf(sf[nf][1]);
            float e2 = __expf(sf[nf][2]);
            float e3 = __expf(sf[nf][3]);
            rs0 += e0 + e1;
            rs1 += e2 + e3;
            ehL[nf] = pack_h2(e0, e1);   // row qb+lr,  cols 8nf+2lc,+1
            ehH[nf] = pack_h2(e2, e3);   // row qb+lr+8
        }

        // O += E @ V (fp16): a-frags direct from registers
        const uint32_t* sVb = dynsm + AV + (mt & 1) * 5120;
#pragma unroll
        for (int ks = 0; ks < 4; ks++) {
            uint32_t a0 = ehL[2 * ks],     a1 = ehH[2 * ks];
            uint32_t a2 = ehL[2 * ks + 1], a3 = ehH[2 * ks + 1];
#pragma unroll
            for (int nf = 0; nf < 16; nf++) {
                uint2 bb = *(const uint2*)&sVb[(nf * 8 + lr) * 40 + ks * 8 + 2 * lc];
                mma_f16(oacc[nf], a0, a1, a2, a3, bb.x, bb.y);
            }
        }
    }
    __syncthreads();   // all PV done -> sQ/sK/sV regions dead

    // issue w_out fp16 tile load into sW (overlaps normalize below)
    uint32_t* sW = dynsm + SW_OFF;    // [256 c][72]
#pragma unroll
    for (int it = 0; it < 16; it++) {
        int u = tid + it * 256;
        int c = u >> 4, seg = u & 15;
        cp16(&sW[c * 72 + seg * 4], g_wo2 + c * 64 + seg * 4);
    }
    CP_COMMIT();

    // rowsum reduce across quad lanes
    rs0 += __shfl_xor_sync(0xffffffffu, rs0, 1);
    rs0 += __shfl_xor_sync(0xffffffffu, rs0, 2);
    rs1 += __shfl_xor_sync(0xffffffffu, rs1, 1);
    rs1 += __shfl_xor_sync(0xffffffffu, rs1, 2);
    const float inv0 = 1.0f / rs0, inv1 = 1.0f / rs1;

    // Normalize, pack half2 (d-pairs native in C-frag), stage permuted [q][72]
    uint32_t* Os = dynsm;   // 128*72 = 9216 words, overlays sQ/sK (dead)
#pragma unroll
    for (int nf = 0; nf < 16; nf++) {
        int w = (nf >> 1) * 8 + 2 * lc + (nf & 1);   // slot of unit 4nf+lc (of 64)
        Os[(qb + lr) * 72 + w]     = pack_h2(oacc[nf][0] * inv0, oacc[nf][1] * inv0);
        Os[(qb + lr + 8) * 72 + w] = pack_h2(oacc[nf][2] * inv1, oacc[nf][3] * inv1);
    }
    CP_WAIT0();
    __syncthreads();        // Os + sW visible to all warps

    // -------- fused projection + residual --------
    // out[c][q] = imgs[c][q] + s * sum_d wout[c][d] * O[d][q]
    const float s = *scale_p;
#pragma unroll
    for (int p = 0; p < 2; p++) {
        const int cb = p * 128 + wid * 16;
        float pacc[16][4];
#pragma unroll
        for (int nf = 0; nf < 16; nf++)
#pragma unroll
            for (int j = 0; j < 4; j++) pacc[nf][j] = 0.0f;
#pragma unroll
        for (int ks = 0; ks < 8; ks++) {
            uint2 aL = *(const uint2*)&sW[(cb + lr) * 72 + ks * 8 + 2 * lc];
            uint2 aH = *(const uint2*)&sW[(cb + lr + 8) * 72 + ks * 8 + 2 * lc];
#pragma unroll
            for (int nf = 0; nf < 16; nf++) {
                uint2 bb = *(const uint2*)&Os[(nf * 8 + lr) * 72 + ks * 8 + 2 * lc];
                mma_f16(pacc[nf], aL.x, aH.x, aL.y, aH.y, bb.x, bb.y);
            }
        }
#pragma unroll
        for (int nf = 0; nf < 16; nf++) {
            int col = nf * 8 + 2 * lc;
            size_t i0 = ((size_t)b * CC + cb + lr) * HWSZ + n0 + col;
            size_t i1 = ((size_t)b * CC + cb + lr + 8) * HWSZ + n0 + col;
            float2 m0 = *(const float2*)&imgs[i0];
            float2 m1 = *(const float2*)&imgs[i1];
            *(float2*)&out[i0] = make_float2(m0.x + s * pacc[nf][0],
                                             m0.y + s * pacc[nf][1]);
            *(float2*)&out[i1] = make_float2(m1.x + s * pacc[nf][2],
                                             m1.y + s * pacc[nf][3]);
        }
    }
}

// ============================================================
extern "C" void kernel_launch(void* const* d_in, const int* in_sizes, int n_in,
                              void* d_out, int out_size) {
    const float* imgs  = (const float*)d_in[0];
    const float* wqkv  = (const float*)d_in[1];
    const float* wout  = (const float*)d_in[2];
    const float* scale = (const float*)d_in[3];
    float* out = (float*)d_out;

    cudaFuncSetAttribute(k_qkv_mma,  cudaFuncAttributeMaxDynamicSharedMemorySize, GEMM_SMEM_BYTES);
    cudaFuncSetAttribute(k_attn_mma, cudaFuncAttributeMaxDynamicSharedMemorySize, SATT_SMEM_BYTES);

    k_qkv_mma<<<dim3(16, 3, 16), 256, GEMM_SMEM_BYTES>>>(imgs, wqkv, wout);

    k_attn_mma<<<dim3(32, 16), 256, SATT_SMEM_BYTES>>>(imgs, scale, out);
}

// round 17
// speedup vs baseline: 1.0863x; 1.0637x over previous
#include <cuda_runtime.h>
#include <cstdint>

// Problem constants
#define BB   16
#define CC   256
#define HH   64
#define WW   64
#define HWSZ 4096     // H*W
#define DQ   32       // C/8
#define DV   128      // C/2
#define OC   192      // 2*DQ + DV
#define MM   1024     // pooled spatial (32*32)

#define LOG2E 1.44269504088896340736f

// Scratch (device globals)
// g_q2 : q channels fp16x2, PRE-SCALED by log2e: [b*16 + unit][hw]
//        unit u = d-pair (2u lo, 2u+1 hi), IDENTITY order
// g_k2 : pooled K fp16x2 [b][m][16 units]   (unit = d-pair, identity)
// g_v2 : pooled V fp16x2 [b][d][512 units]  (unit = m-pair, identity)
// g_wo2: w_out fp16x2 [c][64 units]         (unit = d-pair, PAIR-PERMUTED within
//        8-unit groups: slot s holds unit {0,4,1,5,2,6,3,7}[s] — proj epilogue layout)
__device__ uint32_t g_q2 [BB * 16 * HWSZ];
__device__ uint32_t g_k2 [BB * MM * 16];
__device__ uint32_t g_v2 [BB * DV * (MM / 2)];
__device__ uint32_t g_wo2[CC * (DV / 2)];

// ---- mma helpers ----
// tf32, raw fp32 bits (HMMA reads tf32 subset) — used by k_qkv only
__device__ __forceinline__ void mma_tf32(float* c, const uint32_t* a, const uint32_t* b) {
    asm volatile("mma.sync.aligned.m16n8k8.row.col.f32.tf32.tf32.f32 "
        "{%0,%1,%2,%3}, {%4,%5,%6,%7}, {%8,%9}, {%0,%1,%2,%3};"
        : "+f"(c[0]), "+f"(c[1]), "+f"(c[2]), "+f"(c[3])
        : "r"(a[0]), "r"(a[1]), "r"(a[2]), "r"(a[3]), "r"(b[0]), "r"(b[1]));
}
// fp16 in, fp32 accum
__device__ __forceinline__ void mma_f16(float* c, uint32_t a0, uint32_t a1, uint32_t a2,
                                        uint32_t a3, uint32_t b0, uint32_t b1) {
    asm volatile("mma.sync.aligned.m16n8k16.row.col.f32.f16.f16.f32 "
        "{%0,%1,%2,%3}, {%4,%5,%6,%7}, {%8,%9}, {%0,%1,%2,%3};"
        : "+f"(c[0]), "+f"(c[1]), "+f"(c[2]), "+f"(c[3])
        : "r"(a0), "r"(a1), "r"(a2), "r"(a3), "r"(b0), "r"(b1));
}
__device__ __forceinline__ uint32_t pack_h2(float lo, float hi) {
    uint32_t r;
    asm("cvt.rn.f16x2.f32 %0, %1, %2;" : "=r"(r) : "f"(hi), "f"(lo));
    return r;
}
__device__ __forceinline__ float ex2f(float x) {
    float r;
    asm("ex2.approx.f32 %0, %1;" : "=f"(r) : "f"(x));
    return r;
}
// ldmatrix x4 (b16, non-trans): lanes 8p..8p+7 give row addrs of piece p
__device__ __forceinline__ void ldsm4(uint32_t& r0, uint32_t& r1, uint32_t& r2,
                                      uint32_t& r3, uint32_t saddr) {
    asm volatile("ldmatrix.sync.aligned.m8n8.x4.shared.b16 {%0,%1,%2,%3}, [%4];"
        : "=r"(r0), "=r"(r1), "=r"(r2), "=r"(r3) : "r"(saddr));
}

// ---- cp.async helpers ----
__device__ __forceinline__ void cp16(void* dst, const void* src) {
    uint32_t d = (uint32_t)__cvta_generic_to_shared(dst);
    asm volatile("cp.async.cg.shared.global [%0], [%1], 16;" :: "r"(d), "l"(src) : "memory");
}
#define CP_COMMIT() asm volatile("cp.async.commit_group;" ::: "memory")
#define CP_WAIT0()  asm volatile("cp.async.wait_group 0;" ::: "memory")
#define CP_WAIT1()  asm volatile("cp.async.wait_group 1;" ::: "memory")

extern __shared__ uint32_t dynsm[];

// ============================================================
// K1: qkv GEMM (tf32) + fused pool/pack epilogue.
// by=0: q rows 0-31 -> scale by log2e, fp16-pack -> g_q2;
//       k rows 32-63 -> pool -> g_k2 (fp16x2 identity units)
// by=1/2: v chans -> pool -> g_v2 (fp16x2 identity units)
// ============================================================
#define G_SA(i) ((i) * 2304)              // 64*36
#define G_SB(i) (4608 + (i) * 8448)       // 32*264
#define GEMM_SMEM_BYTES ((4608 + 2 * 8448) * 4)   // 86016

__global__ void __launch_bounds__(256) k_qkv_mma(const float* __restrict__ imgs,
                                                 const float* __restrict__ wq,
                                                 const float* __restrict__ wout) {
    const int b  = blockIdx.z;
    const int o0 = blockIdx.y * 64;
    const int n0 = blockIdx.x * 256;
    const int tid = threadIdx.x, lane = tid & 31, wid = tid >> 5;
    const int lr = lane >> 2, lc = lane & 3;
    const int wm = (wid >> 2) * 32;
    const int wn = (wid & 3) * 64;
    const float* X = imgs + (size_t)b * CC * HWSZ;

    auto prefetch = [&](int ibuf, int kc) {
        uint32_t* sA = dynsm + G_SA(ibuf);
        uint32_t* sB = dynsm + G_SB(ibuf);
#pragma unroll
        for (int it = 0; it < 2; it++) {
            int u = tid + it * 256;
            int o = u >> 3, cv = u & 7;
            cp16(&sA[o * 36 + cv * 4], wq + (size_t)(o0 + o) * CC + kc + cv * 4);
        }
#pragma unroll
        for (int it = 0; it < 8; it++) {
            int u = tid + it * 256;
            int c = u >> 6, nv = u & 63;
            cp16(&sB[c * 264 + nv * 4], X + (size_t)(kc + c) * HWSZ + n0 + nv * 4);
        }
        CP_COMMIT();
    };

    float acc[2][8][4];
#pragma unroll
    for (int mf = 0; mf < 2; mf++)
#pragma unroll
        for (int nf = 0; nf < 8; nf++)
#pragma unroll
            for (int j = 0; j < 4; j++) acc[mf][nf][j] = 0.0f;

    prefetch(0, 0);

    // w_out fp16 packing (pair-permuted): 16 CTAs (by=0, bx=0), rows [b*16, +16)
    if (o0 == 0 && blockIdx.x == 0) {
#pragma unroll
        for (int i = 0; i < 4; i++) {
            int idx = tid + i * 256;
            int c  = b * 16 + (idx >> 6);
            int gu = idx & 63;
            int g = gu >> 3, sl = gu & 7;
            int pu = (sl & 1) ? (sl >> 1) + 4 : (sl >> 1);
            int cu = g * 8 + pu;
            float2 w2 = *(const float2*)&wout[(size_t)c * DV + 2 * cu];
            g_wo2[c * 64 + gu] = pack_h2(w2.x, w2.y);
        }
    }

    for (int ic = 0; ic < 8; ic++) {
        if (ic + 1 < 8) { prefetch((ic + 1) & 1, (ic + 1) * 32); CP_WAIT1(); }
        else            { CP_WAIT0(); }
        __syncthreads();
        const uint32_t* sA = dynsm + G_SA(ic & 1);
        const uint32_t* sB = dynsm + G_SB(ic & 1);
#pragma unroll
        for (int k8 = 0; k8 < 32; k8 += 8) {
            uint32_t a[2][4];
            const int ar = wm + lr;
            const int ac = k8 + lc;
#pragma unroll
            for (int mf = 0; mf < 2; mf++) {
                int r = ar + mf * 16;
                a[mf][0] = sA[r * 36 + ac];
                a[mf][1] = sA[(r + 8) * 36 + ac];
                a[mf][2] = sA[r * 36 + ac + 4];
                a[mf][3] = sA[(r + 8) * 36 + ac + 4];
            }
#pragma unroll
            for (int nf = 0; nf < 8; nf++) {
                int bn = wn + nf * 8 + lr;
                uint32_t bf[2];
                bf[0] = sB[(k8 + lc) * 264 + bn];
                bf[1] = sB[(k8 + 4 + lc) * 264 + bn];
                mma_tf32(acc[0][nf], a[0], bf);
                mma_tf32(acc[1][nf], a[1], bf);
            }
        }
        __syncthreads();
    }

    // -------- fused epilogue: stage ALL 64 rows, then pack/pool --------
    float* stg = (float*)dynsm;                 // [64 rows][260]
    const int bxm = blockIdx.x * 64;            // pooled-m base
#pragma unroll
    for (int mf = 0; mf < 2; mf++)
#pragma unroll
        for (int nf = 0; nf < 8; nf++) {
            int r   = wm + mf * 16 + lr;
            int col = wn + nf * 8 + 2 * lc;
            *(float2*)&stg[r * 260 + col] =
                make_float2(acc[mf][nf][0], acc[mf][nf][1]);
            *(float2*)&stg[(r + 8) * 260 + col] =
                make_float2(acc[mf][nf][2], acc[mf][nf][3]);
        }
    __syncthreads();

    if (o0 == 0) {
        // q: scale by log2e, fp16-pack d-pairs (identity) -> g_q2[b*16+u][hw]
#pragma unroll
        for (int u = 0; u < 16; u++) {
            float v0 = stg[(2 * u) * 260 + tid] * LOG2E;
            float v1 = stg[(2 * u + 1) * 260 + tid] * LOG2E;
            g_q2[((size_t)b * 16 + u) * HWSZ + n0 + tid] = pack_h2(v0, v1);
        }
        // k pool -> g_k2[b][m][16 units identity]
#pragma unroll
        for (int i = 0; i < 4; i++) {
            int idx = tid + i * 256;
            int mloc = idx >> 4, unit = idx & 15;
            int myl = mloc >> 5, mx = mloc & 31;
            const float* s0 = stg + (32 + 2 * unit) * 260 + myl * 128 + 2 * mx;
            const float* s1 = s0 + 260;
            float v0 = fmaxf(fmaxf(s0[0], s0[1]), fmaxf(s0[64], s0[65]));
            float v1 = fmaxf(fmaxf(s1[0], s1[1]), fmaxf(s1[64], s1[65]));
            g_k2[((size_t)b * MM + bxm + mloc) * 16 + unit] = pack_h2(v0, v1);
        }
    } else {
        const int chb = o0 - 64;     // v channel base (0 or 64)
        // v pool -> g_v2[b][d][m-units identity]
#pragma unroll
        for (int i = 0; i < 8; i++) {
            int idx = tid + i * 256;
            int ch = idx >> 5, unit = idx & 31;
            float vv[2];
#pragma unroll
            for (int h = 0; h < 2; h++) {
                int m = 2 * unit + h;
                int myl = m >> 5, mx = m & 31;
                const float* s0 = stg + ch * 260 + myl * 128 + 2 * mx;
                vv[h] = fmaxf(fmaxf(s0[0], s0[1]), fmaxf(s0[64], s0[65]));
            }
            g_v2[((size_t)b * DV + chb + ch) * (MM / 2) + blockIdx.x * 32 + unit] =
                pack_h2(vv[0], vv[1]);
        }
    }
}

// ============================================================
// K3: flash attention (all-fp16 mma) + fused projection + residual.
// CTA 256 thr = 8 warps x 16q, 128-query tile, grid (32,16), 2 CTA/SM.
// S = exp2(Q' K) with Q' = q*log2e baked in -> bare ex2.approx.
// E stays in registers (S C-frag == PV A-frag, thread-local).
// K/V b-frags via ldmatrix.x4 on identity fp16x2 layouts.
// SMEM (words): sQ[16 u][132 q] | sK 2x[64 m][20] | sV 2x[128 d][36]
// Epilogue: Os[128 q][72] (0..9216) | sW[256 c][72] (9216..27648)
// ============================================================
#define AQ 0
#define AK 2112                       // 16*132
#define AV 4672                       // AK + 2*1280
#define SW_OFF 9216
#define SATT_SMEM_BYTES ((SW_OFF + 256 * 72) * 4)    // 110592

__global__ void __launch_bounds__(256, 2) k_attn_mma(const float* __restrict__ imgs,
                                                     const float* __restrict__ scale_p,
                                                     float* __restrict__ out) {
    uint32_t* sQ = dynsm + AQ;

    const int b   = blockIdx.y;
    const int n0  = blockIdx.x * 128;
    const int tid = threadIdx.x, lane = tid & 31, wid = tid >> 5;
    const int qb  = wid * 16;
    const int lr  = lane >> 2;
    const int lc  = lane & 3;
    // ldmatrix lane geometry: piece p = lane>>3, row r = lane&7
    const int lp = lane >> 3, lrr = lane & 7;
    const uint32_t smem_base = (uint32_t)__cvta_generic_to_shared(dynsm);
    // lane byte-offsets within a tile: row 8*(p>>1)+r, col-half (p&1)*4 words
    const uint32_t k_lane = ((8 * (lp >> 1) + lrr) * 20 + (lp & 1) * 4) * 4;
    const uint32_t v_lane = ((8 * (lp >> 1) + lrr) * 36 + (lp & 1) * 4) * 4;

    // tile loaders
    auto load_k = [&](int mt) {    // 64 rows x 16 words -> 256 cp16
        uint32_t* dst = dynsm + AK + (mt & 1) * 1280;
        int ml = tid >> 2, c = tid & 3;
        cp16(&dst[ml * 20 + c * 4],
             g_k2 + ((size_t)b * MM + mt * 64 + ml) * 16 + c * 4);
    };
    auto load_v = [&](int mt) {    // 128 rows x 32 words -> 1024 cp16
        uint32_t* dst = dynsm + AV + (mt & 1) * 4608;
#pragma unroll
        for (int it = 0; it < 4; it++) {
            int u = tid + it * 256;
            int d = u >> 3, c = u & 7;
            cp16(&dst[d * 36 + c * 4],
                 g_v2 + ((size_t)b * DV + d) * (MM / 2) + mt * 32 + c * 4);
        }
    };

    // prologue: Q + K0 + V0
#pragma unroll
    for (int it = 0; it < 2; it++) {   // 16 rows x 128 words -> 512 cp16
        int u = tid + it * 256;
        int s = u >> 5, c = u & 31;
        cp16(&sQ[s * 132 + c * 4], g_q2 + ((size_t)b * 16 + s) * HWSZ + n0 + c * 4);
    }
    load_k(0);
    load_v(0);
    CP_COMMIT();
    CP_WAIT0();
    __syncthreads();

    // preload Q a-frags (fp16): a0/a2 = units 8ks+lc / 8ks+4+lc (identity slots)
    uint32_t qa[2][4];
#pragma unroll
    for (int ks = 0; ks < 2; ks++) {
        qa[ks][0] = sQ[(8 * ks + lc) * 132 + qb + lr];
        qa[ks][1] = sQ[(8 * ks + lc) * 132 + qb + lr + 8];
        qa[ks][2] = sQ[(8 * ks + 4 + lc) * 132 + qb + lr];
        qa[ks][3] = sQ[(8 * ks + 4 + lc) * 132 + qb + lr + 8];
    }

    float oacc[16][4];
#pragma unroll
    for (int nf = 0; nf < 16; nf++)
#pragma unroll
        for (int j = 0; j < 4; j++) oacc[nf][j] = 0.0f;
    float rs0 = 0.0f, rs1 = 0.0f;

    for (int mt = 0; mt < 16; mt++) {
        if (mt > 0) CP_WAIT0();
        __syncthreads();          // tiles visible; all warps done with other bufs

        if (mt + 1 < 16) {
            load_k(mt + 1);
            load_v(mt + 1);
            CP_COMMIT();
        }

        // S' = Q' @ K^T (fp16, k=32 -> 2 k16-steps), exp2 immediately per nf-pair
        const uint32_t kb = smem_base + (AK + (mt & 1) * 1280) * 4 + k_lane;
        uint32_t ehL[8], ehH[8];
#pragma unroll
        for (int nfp = 0; nfp < 4; nfp++) {
            float s2[2][4];
#pragma unroll
            for (int j = 0; j < 2; j++)
#pragma unroll
                for (int q = 0; q < 4; q++) s2[j][q] = 0.0f;
#pragma unroll
            for (int ks = 0; ks < 2; ks++) {
                uint32_t b0, b1, b2, b3;
                ldsm4(b0, b1, b2, b3, kb + nfp * 1280 + ks * 32);
                mma_f16(s2[0], qa[ks][0], qa[ks][1], qa[ks][2], qa[ks][3], b0, b1);
                mma_f16(s2[1], qa[ks][0], qa[ks][1], qa[ks][2], qa[ks][3], b2, b3);
            }
#pragma unroll
            for (int j = 0; j < 2; j++) {
                float e0 = ex2f(s2[j][0]);
                float e1 = ex2f(s2[j][1]);
                float e2 = ex2f(s2[j][2]);
                float e3 = ex2f(s2[j][3]);
                rs0 += e0 + e1;
                rs1 += e2 + e3;
                ehL[2 * nfp + j] = pack_h2(e0, e1);
                ehH[2 * nfp + j] = pack_h2(e2, e3);
            }
        }

        // O += E @ V (fp16): A from registers, B via ldmatrix
        const uint32_t vb = smem_base + (AV + (mt & 1) * 4608) * 4 + v_lane;
#pragma unroll
        for (int ks = 0; ks < 4; ks++) {
            uint32_t a0 = ehL[2 * ks],     a1 = ehH[2 * ks];
            uint32_t a2 = ehL[2 * ks + 1], a3 = ehH[2 * ks + 1];
#pragma unroll
            for (int nfp = 0; nfp < 8; nfp++) {
                uint32_t b0, b1, b2, b3;
                ldsm4(b0, b1, b2, b3, vb + nfp * 2304 + ks * 32);
                mma_f16(oacc[2 * nfp],     a0, a1, a2, a3, b0, b1);
                mma_f16(oacc[2 * nfp + 1], a0, a1, a2, a3, b2, b3);
            }
        }
    }
    __syncthreads();   // all PV done -> sQ/sK/sV regions dead

    // issue w_out fp16 tile load into sW (overlaps normalize below)
    uint32_t* sW = dynsm + SW_OFF;    // [256 c][72], pair-permuted units
#pragma unroll
    for (int it = 0; it < 16; it++) {
        int u = tid + it * 256;
        int c = u >> 4, seg = u & 15;
        cp16(&sW[c * 72 + seg * 4], g_wo2 + c * 64 + seg * 4);
    }
    CP_COMMIT();

    // rowsum reduce across quad lanes
    rs0 += __shfl_xor_sync(0xffffffffu, rs0, 1);
    rs0 += __shfl_xor_sync(0xffffffffu, rs0, 2);
    rs1 += __shfl_xor_sync(0xffffffffu, rs1, 1);
    rs1 += __shfl_xor_sync(0xffffffffu, rs1, 2);
    const float inv0 = 1.0f / rs0, inv1 = 1.0f / rs1;

    // Normalize, pack half2 (d-pairs native in C-frag), stage PAIR-PERMUTED [q][72]
    uint32_t* Os = dynsm;   // 9216 words, overlays dead main-loop tiles
#pragma unroll
    for (int nf = 0; nf < 16; nf++) {
        int w = (nf >> 1) * 8 + 2 * lc + (nf & 1);   // slot of unit 4nf+lc (of 64)
        Os[(qb + lr) * 72 + w]     = pack_h2(oacc[nf][0] * inv0, oacc[nf][1] * inv0);
        Os[(qb + lr + 8) * 72 + w] = pack_h2(oacc[nf][2] * inv1, oacc[nf][3] * inv1);
    }
    CP_WAIT0();
    __syncthreads();        // Os + sW visible to all warps

    // -------- fused projection + residual --------
    const float s = *scale_p;
#pragma unroll
    for (int p = 0; p < 2; p++) {
        const int cb = p * 128 + wid * 16;
        float pacc[16][4];
#pragma unroll
        for (int nf = 0; nf < 16; nf++)
#pragma unroll
            for (int j = 0; j < 4; j++) pacc[nf][j] = 0.0f;
#pragma unroll
        for (int ks = 0; ks < 8; ks++) {
            uint2 aL = *(const uint2*)&sW[(cb + lr) * 72 + ks * 8 + 2 * lc];
            uint2 aH = *(const uint2*)&sW[(cb + lr + 8) * 72 + ks * 8 + 2 * lc];
#pragma unroll
            for (int nf = 0; nf < 16; nf++) {
                uint2 bb = *(const uint2*)&Os[(nf * 8 + lr) * 72 + ks * 8 + 2 * lc];
                mma_f16(pacc[nf], aL.x, aH.x, aL.y, aH.y, bb.x, bb.y);
            }
        }
#pragma unroll
        for (int nf = 0; nf < 16; nf++) {
            int col = nf * 8 + 2 * lc;
            size_t i0 = ((size_t)b * CC + cb + lr) * HWSZ + n0 + col;
            size_t i1 = ((size_t)b * CC + cb + lr + 8) * HWSZ + n0 + col;
            float2 m0 = *(const float2*)&imgs[i0];
            float2 m1 = *(const float2*)&imgs[i1];
            *(float2*)&out[i0] = make_float2(m0.x + s * pacc[nf][0],
                                             m0.y + s * pacc[nf][1]);
            *(float2*)&out[i1] = make_float2(m1.x + s * pacc[nf][2],
                                             m1.y + s * pacc[nf][3]);
        }
    }
}

// ============================================================
extern "C" void kernel_launch(void* const* d_in, const int* in_sizes, int n_in,
                              void* d_out, int out_size) {
    const float* imgs  = (const float*)d_in[0];
    const float* wqkv  = (const float*)d_in[1];
    const float* wout  = (const float*)d_in[2];
    const float* scale = (const float*)d_in[3];
    float* out = (float*)d_out;

    cudaFuncSetAttribute(k_qkv_mma,  cudaFuncAttributeMaxDynamicSharedMemorySize, GEMM_SMEM_BYTES);
    cudaFuncSetAttribute(k_attn_mma, cudaFuncAttributeMaxDynamicSharedMemorySize, SATT_SMEM_BYTES);

    k_qkv_mma<<<dim3(16, 3, 16), 256, GEMM_SMEM_BYTES>>>(imgs, wqkv, wout);

    k_attn_mma<<<dim3(32, 16), 256, SATT_SMEM_BYTES>>>(imgs, scale, out);
}